// round 4
// baseline (speedup 1.0000x reference)
#include <cuda_runtime.h>
#include <stdint.h>

#define B_   2
#define L_   2048
#define D_   1024
#define H_   16
#define N3_  3072
#define MT_  4096
#define LOG2E 1.4426950408889634f

// scratch (allocation-free rule: device globals)
__device__ float g_qkv[(size_t)MT_ * N3_];   // tf32-rounded qkv
__device__ float g_z[(size_t)MT_ * D_];      // tf32-rounded attn output

__device__ __forceinline__ uint32_t tf32u(float x) {
    uint32_t u; asm("cvt.rna.tf32.f32 %0, %1;" : "=r"(u) : "f"(x));
    return u;
}
__device__ __forceinline__ float to_tf32(float x) {
    return __uint_as_float(tf32u(x));
}

__device__ __forceinline__ void mma8(float* d, const uint32_t* a, const uint32_t* b) {
    asm volatile(
        "mma.sync.aligned.m16n8k8.row.col.f32.tf32.tf32.f32 "
        "{%0,%1,%2,%3}, {%4,%5,%6,%7}, {%8,%9}, {%0,%1,%2,%3};\n"
        : "+f"(d[0]), "+f"(d[1]), "+f"(d[2]), "+f"(d[3])
        : "r"(a[0]), "r"(a[1]), "r"(a[2]), "r"(a[3]), "r"(b[0]), "r"(b[1]));
}

// cp.async helpers
__device__ __forceinline__ void cpa(void* s, const void* g) {
    uint32_t sa = (uint32_t)__cvta_generic_to_shared(s);
    asm volatile("cp.async.cg.shared.global [%0], [%1], 16;\n" :: "r"(sa), "l"(g));
}
__device__ __forceinline__ void cpcommit() { asm volatile("cp.async.commit_group;\n"); }
template<int N> __device__ __forceinline__ void cpwait() {
    asm volatile("cp.async.wait_group %0;\n" :: "n"(N));
}

// fast exp on FMA/ALU pipes. x <= 0 here.
__device__ __forceinline__ float fexp(float x) {
    x = fmaxf(x, -80.0f);
    float t = fmaf(x, LOG2E, 12582912.0f);
    float n = t - 12582912.0f;
    float f = fmaf(x, LOG2E, -n);
    float p = 1.3333558e-3f;
    p = fmaf(p, f, 9.6181291e-3f);
    p = fmaf(p, f, 5.5504109e-2f);
    p = fmaf(p, f, 2.4022651e-1f);
    p = fmaf(p, f, 6.9314718e-1f);
    p = fmaf(p, f, 1.0f);
    int ni = __float_as_int(t) - 0x4B400000;
    return __int_as_float(__float_as_int(p) + (ni << 23));
}

// ---------------------------------------------------------------------------
// tf32 mma GEMM, 4-stage cp.async pipeline. C[M,N] = A@B (+bias, opt round).
// 128x128 tile, K-chunk 16, 8 warps 2(m)x4(n), warp tile 64x32.
// tf32 RNA rounding applied at fragment load (FMA pipe is idle).
// Stage layout: As[128][20] (pad4 -> conflict-free frags), Bs[16][136] (pad8).
// ---------------------------------------------------------------------------
#define KC 16
#define A_ST 20
#define B_ST 136
#define STG_F (128 * A_ST + KC * B_ST)       // floats per stage = 4736
#define GEMM_SMEM (4 * STG_F * 4)            // 75776 bytes

template<bool BIAS, bool ROUND>
__global__ __launch_bounds__(256)
void mma_gemm(const float* __restrict__ A, const float* __restrict__ Bm,
              const float* __restrict__ bias, float* __restrict__ C,
              int M, int N, int K)
{
    extern __shared__ float sm[];
    const int tid  = threadIdx.x;
    const int w    = tid >> 5, lane = tid & 31;
    const int g    = lane >> 2, tg = lane & 3;
    const int wm   = (w >> 2) * 64;
    const int wn   = (w & 3) * 32;
    const int row0 = blockIdx.y * 128, col0 = blockIdx.x * 128;

    const int ar = tid >> 2,  ac = (tid & 3) * 4;    // A: 128 x 16, 2 ld/thr
    const int br = tid >> 5,  bc = (tid & 31) * 4;   // B: 16 x 128, 2 ld/thr

    float acc[16][4];
    #pragma unroll
    for (int i = 0; i < 16; i++)
        #pragma unroll
        for (int j = 0; j < 4; j++) acc[i][j] = 0.f;

    const int nIter = K / KC;

    auto load_stage = [&](int it) {
        const int k0 = it * KC;
        float* as = sm + (it & 3) * STG_F;
        float* bs = as + 128 * A_ST;
        #pragma unroll
        for (int i = 0; i < 2; i++) {
            cpa(&as[(ar + 64 * i) * A_ST + ac],
                &A[(size_t)(row0 + ar + 64 * i) * K + k0 + ac]);
            cpa(&bs[(br + 8 * i) * B_ST + bc],
                &Bm[(size_t)(k0 + br + 8 * i) * N + col0 + bc]);
        }
    };

    load_stage(0); cpcommit();
    load_stage(1); cpcommit();
    load_stage(2); cpcommit();

    for (int it = 0; it < nIter; it++) {
        cpwait<2>();
        __syncthreads();
        if (it + 3 < nIter) load_stage(it + 3);
        cpcommit();

        const float* as = sm + (it & 3) * STG_F;
        const float* bs = as + 128 * A_ST;
        #pragma unroll
        for (int k8 = 0; k8 < 2; k8++) {
            const int kk = k8 * 8;
            uint32_t a[4][4], b[4][2];
            #pragma unroll
            for (int mt = 0; mt < 4; mt++) {
                const int m = wm + mt * 16;
                a[mt][0] = tf32u(as[(m + g    ) * A_ST + kk + tg]);
                a[mt][1] = tf32u(as[(m + g + 8) * A_ST + kk + tg]);
                a[mt][2] = tf32u(as[(m + g    ) * A_ST + kk + tg + 4]);
                a[mt][3] = tf32u(as[(m + g + 8) * A_ST + kk + tg + 4]);
            }
            #pragma unroll
            for (int nt = 0; nt < 4; nt++) {
                const int n = wn + nt * 8;
                b[nt][0] = tf32u(bs[(kk + tg    ) * B_ST + n + g]);
                b[nt][1] = tf32u(bs[(kk + tg + 4) * B_ST + n + g]);
            }
            #pragma unroll
            for (int mt = 0; mt < 4; mt++)
                #pragma unroll
                for (int nt = 0; nt < 4; nt++)
                    mma8(acc[mt * 4 + nt], a[mt], b[nt]);
        }
    }

    #pragma unroll
    for (int mt = 0; mt < 4; mt++) {
        #pragma unroll
        for (int nt = 0; nt < 4; nt++) {
            int r = row0 + wm + mt * 16 + g;
            int c = col0 + wn + nt * 8 + 2 * tg;
            float v0 = acc[mt * 4 + nt][0], v1 = acc[mt * 4 + nt][1];
            float v2 = acc[mt * 4 + nt][2], v3 = acc[mt * 4 + nt][3];
            if (BIAS) {
                float b0 = bias[c], b1 = bias[c + 1];
                v0 += b0; v1 += b1; v2 += b0; v3 += b1;
            }
            if (ROUND) {
                v0 = to_tf32(v0); v1 = to_tf32(v1);
                v2 = to_tf32(v2); v3 = to_tf32(v3);
            }
            *(float2*)&C[(size_t)r * N + c]       = make_float2(v0, v1);
            *(float2*)&C[(size_t)(r + 8) * N + c] = make_float2(v2, v3);
        }
    }
}

// ---------------------------------------------------------------------------
// Flash attention (tf32 mma), 2-stage cp.async K/V pipeline, Q frags hoisted
// to registers, mask prefetched ahead of the S-mma.
//   out = sum(e^{s-m}*mask*v) / (sum(e^{s-m}*mask) + eps*sum(e^{s-m}))
// Block: 128 q-rows x one (b,h); 8 warps; warp owns 16 q-rows (softmax
// fully warp-local). 64 keys per iteration.
// ---------------------------------------------------------------------------
#define QS_OFF 0                       // [128][68]
#define KS_OFF 8704                    // [2][64][68]
#define VS_OFF (8704 + 2 * 4352)      // [2][64][72]
#define PS_OFF (VS_OFF + 2 * 4608)    // [128][68]
#define ATTN_SMEM ((PS_OFF + 8704) * 4)   // 141312 bytes

__global__ __launch_bounds__(256)
void attn_mma(const float* __restrict__ qkv, const float* __restrict__ mask,
              float* __restrict__ z)
{
    extern __shared__ float sm[];
    float* Qs = sm + QS_OFF;
    float* Ps = sm + PS_OFF;

    const int tid = threadIdx.x;
    const int w = tid >> 5, lane = tid & 31;
    const int g = lane >> 2, tg = lane & 3;
    const int m0 = w * 16;
    const int bb = blockIdx.y >> 4;
    const int h  = blockIdx.y & 15;
    const int qi0 = blockIdx.x * 128;
    const size_t tok0 = (size_t)bb * L_ + qi0;
    const int hc = h * 64;

    const int lr = tid >> 4, lc = (tid & 15) * 4;   // 256-thr tile loader idx

    auto load_kv = [&](int kt) {
        const size_t ktok = (size_t)bb * L_ + kt * 64;
        float* ks = sm + KS_OFF + (kt & 1) * 4352;
        float* vs = sm + VS_OFF + (kt & 1) * 4608;
        #pragma unroll
        for (int i = 0; i < 4; i++) {
            int r = lr + 16 * i;
            cpa(&ks[r * 68 + lc], &qkv[(ktok + r) * N3_ + 1024 + hc + lc]);
            cpa(&vs[r * 72 + lc], &qkv[(ktok + r) * N3_ + 2048 + hc + lc]);
        }
    };

    // prologue: Q + stage 0 (group 0), stage 1 (group 1)
    #pragma unroll
    for (int i = 0; i < 8; i++) {
        int r = lr + 16 * i;
        cpa(&Qs[r * 68 + lc], &qkv[(tok0 + r) * N3_ + hc + lc]);
    }
    load_kv(0); cpcommit();
    load_kv(1); cpcommit();
    cpwait<1>();
    __syncthreads();

    // hoist Q fragments (invariant over all K tiles)
    uint32_t qa[8][4];
    #pragma unroll
    for (int k8 = 0; k8 < 8; k8++) {
        const int kk = k8 * 8;
        qa[k8][0] = __float_as_uint(Qs[(m0 + g    ) * 68 + kk + tg]);
        qa[k8][1] = __float_as_uint(Qs[(m0 + g + 8) * 68 + kk + tg]);
        qa[k8][2] = __float_as_uint(Qs[(m0 + g    ) * 68 + kk + tg + 4]);
        qa[k8][3] = __float_as_uint(Qs[(m0 + g + 8) * 68 + kk + tg + 4]);
    }

    float acc[8][4];
    #pragma unroll
    for (int i = 0; i < 8; i++)
        #pragma unroll
        for (int j = 0; j < 4; j++) acc[i][j] = 0.f;
    float mp0 = -1e30f, mp1 = -1e30f;
    float se0 = 0.f, se1 = 0.f, sq0 = 0.f, sq1 = 0.f;

    const float* mrow0 = mask + (tok0 + m0 + g) * L_ + 2 * tg;
    const float* mrow1 = mrow0 + 8 * (size_t)L_;

    for (int kt = 0; kt < L_ / 64; kt++) {
        const int kj0 = kt * 64;
        const float* Ks = sm + KS_OFF + (kt & 1) * 4352;
        const float* Vs = sm + VS_OFF + (kt & 1) * 4608;

        // prefetch mask (consumed after S-mma)
        float2 mk0[8], mk1[8];
        #pragma unroll
        for (int nt = 0; nt < 8; nt++) {
            mk0[nt] = *(const float2*)&mrow0[kj0 + nt * 8];
            mk1[nt] = *(const float2*)&mrow1[kj0 + nt * 8];
        }

        // S = Q @ K^T : m16 x n64
        float s[8][4];
        #pragma unroll
        for (int nt = 0; nt < 8; nt++)
            #pragma unroll
            for (int j = 0; j < 4; j++) s[nt][j] = 0.f;
        #pragma unroll
        for (int k8 = 0; k8 < 8; k8++) {
            const int kk = k8 * 8;
            #pragma unroll
            for (int nt = 0; nt < 8; nt++) {
                uint32_t b[2];
                b[0] = __float_as_uint(Ks[(nt * 8 + g) * 68 + kk + tg]);
                b[1] = __float_as_uint(Ks[(nt * 8 + g) * 68 + kk + tg + 4]);
                mma8(s[nt], qa[k8], b);
            }
        }

        // warp-local online softmax (rows g, g+8)
        float r0 = -1e30f, r1 = -1e30f;
        #pragma unroll
        for (int nt = 0; nt < 8; nt++) {
            s[nt][0] *= 0.125f; s[nt][1] *= 0.125f;
            s[nt][2] *= 0.125f; s[nt][3] *= 0.125f;
            r0 = fmaxf(r0, fmaxf(s[nt][0], s[nt][1]));
            r1 = fmaxf(r1, fmaxf(s[nt][2], s[nt][3]));
        }
        r0 = fmaxf(r0, __shfl_xor_sync(0xffffffffu, r0, 1));
        r0 = fmaxf(r0, __shfl_xor_sync(0xffffffffu, r0, 2));
        r1 = fmaxf(r1, __shfl_xor_sync(0xffffffffu, r1, 1));
        r1 = fmaxf(r1, __shfl_xor_sync(0xffffffffu, r1, 2));

        float mn0 = fmaxf(mp0, r0), mn1 = fmaxf(mp1, r1);
        float c0 = fexp(mp0 - mn0), c1 = fexp(mp1 - mn1);
        mp0 = mn0; mp1 = mn1;

        float pe0 = 0.f, pe1 = 0.f, pm0 = 0.f, pm1 = 0.f;
        #pragma unroll
        for (int nt = 0; nt < 8; nt++) {
            float p00 = fexp(s[nt][0] - mn0);
            float p01 = fexp(s[nt][1] - mn0);
            float p10 = fexp(s[nt][2] - mn1);
            float p11 = fexp(s[nt][3] - mn1);
            pe0 += p00 + p01; pe1 += p10 + p11;
            float q00 = p00 * mk0[nt].x, q01 = p01 * mk0[nt].y;
            float q10 = p10 * mk1[nt].x, q11 = p11 * mk1[nt].y;
            pm0 += q00 + q01; pm1 += q10 + q11;
            *(float2*)&Ps[(m0 + g    ) * 68 + nt * 8 + 2 * tg] =
                make_float2(to_tf32(q00), to_tf32(q01));
            *(float2*)&Ps[(m0 + g + 8) * 68 + nt * 8 + 2 * tg] =
                make_float2(to_tf32(q10), to_tf32(q11));
        }
        pe0 += __shfl_xor_sync(0xffffffffu, pe0, 1);
        pe0 += __shfl_xor_sync(0xffffffffu, pe0, 2);
        pe1 += __shfl_xor_sync(0xffffffffu, pe1, 1);
        pe1 += __shfl_xor_sync(0xffffffffu, pe1, 2);
        pm0 += __shfl_xor_sync(0xffffffffu, pm0, 1);
        pm0 += __shfl_xor_sync(0xffffffffu, pm0, 2);
        pm1 += __shfl_xor_sync(0xffffffffu, pm1, 1);
        pm1 += __shfl_xor_sync(0xffffffffu, pm1, 2);
        se0 = se0 * c0 + pe0; se1 = se1 * c1 + pe1;
        sq0 = sq0 * c0 + pm0; sq1 = sq1 * c1 + pm1;
        #pragma unroll
        for (int nt = 0; nt < 8; nt++) {
            acc[nt][0] *= c0; acc[nt][1] *= c0;
            acc[nt][2] *= c1; acc[nt][3] *= c1;
        }
        __syncwarp();   // Ps rows are warp-private

        // acc += P @ V : m16 x n64(dh)
        #pragma unroll
        for (int k8 = 0; k8 < 8; k8++) {
            const int kk = k8 * 8;
            uint32_t a[4];
            a[0] = __float_as_uint(Ps[(m0 + g    ) * 68 + kk + tg]);
            a[1] = __float_as_uint(Ps[(m0 + g + 8) * 68 + kk + tg]);
            a[2] = __float_as_uint(Ps[(m0 + g    ) * 68 + kk + tg + 4]);
            a[3] = __float_as_uint(Ps[(m0 + g + 8) * 68 + kk + tg + 4]);
            #pragma unroll
            for (int nt = 0; nt < 8; nt++) {
                uint32_t b[2];
                b[0] = __float_as_uint(Vs[(kk + tg    ) * 72 + nt * 8 + g]);
                b[1] = __float_as_uint(Vs[(kk + tg + 4) * 72 + nt * 8 + g]);
                mma8(acc[nt], a, b);
            }
        }

        // stage next K/V tile
        if (kt < L_ / 64 - 1) {
            __syncthreads();                      // all warps done with stage kt
            if (kt + 2 < L_ / 64) load_kv(kt + 2);
            cpcommit();
            cpwait<1>();                          // stage kt+1 data arrived
            __syncthreads();                      // ... and visible to all warps
        }
    }

    // epilogue: renorm, tf32-round for out-proj, write z
    float inv0 = 1.0f / (sq0 + 1e-10f * se0 + 1e-30f);
    float inv1 = 1.0f / (sq1 + 1e-10f * se1 + 1e-30f);
    #pragma unroll
    for (int nt = 0; nt < 8; nt++) {
        int c = hc + nt * 8 + 2 * tg;
        *(float2*)&z[(tok0 + m0 + g) * D_ + c] =
            make_float2(to_tf32(acc[nt][0] * inv0), to_tf32(acc[nt][1] * inv0));
        *(float2*)&z[(tok0 + m0 + g + 8) * D_ + c] =
            make_float2(to_tf32(acc[nt][2] * inv1), to_tf32(acc[nt][3] * inv1));
    }
}

// ---------------------------------------------------------------------------
extern "C" void kernel_launch(void* const* d_in, const int* in_sizes, int n_in,
                              void* d_out, int out_size)
{
    const float* x    = (const float*)d_in[0];
    const float* mask = (const float*)d_in[1];
    const float* Wqkv = (const float*)d_in[2];
    const float* Wout = (const float*)d_in[3];
    const float* bout = (const float*)d_in[4];
    float* out = (float*)d_out;

    float *qkvp, *zp;
    cudaGetSymbolAddress((void**)&qkvp, g_qkv);
    cudaGetSymbolAddress((void**)&zp,   g_z);

    cudaFuncSetAttribute(mma_gemm<false, true>,
                         cudaFuncAttributeMaxDynamicSharedMemorySize, GEMM_SMEM);
    cudaFuncSetAttribute(mma_gemm<true, false>,
                         cudaFuncAttributeMaxDynamicSharedMemorySize, GEMM_SMEM);
    cudaFuncSetAttribute(attn_mma,
                         cudaFuncAttributeMaxDynamicSharedMemorySize, ATTN_SMEM);

    // 1) QKV projection (tf32 rounding fused at fragment load; epilogue rounds)
    mma_gemm<false, true><<<dim3(N3_ / 128, MT_ / 128), 256, GEMM_SMEM>>>(
        x, Wqkv, nullptr, qkvp, MT_, N3_, D_);

    // 2) masked flash attention
    attn_mma<<<dim3(L_ / 128, B_ * H_), 256, ATTN_SMEM>>>(qkvp, mask, zp);

    // 3) output projection + bias (exact fp32 output)
    mma_gemm<true, false><<<dim3(D_ / 128, MT_ / 128), 256, GEMM_SMEM>>>(
        zp, Wout, bout, out, MT_, D_, D_);
}